// round 12
// baseline (speedup 1.0000x reference)
#include <cuda_runtime.h>
#include <cstdint>

// SpikeFP8MulToFP32 — R12: whole-chip read/write phase separation.
//   A, B: [N, 8] float 0/1 bit-vectors of fp8 e4m3 (order S,E3..E0,M2,M1,M0)
//   out : [N, 32] float 0/1 bit-vector of fp32(A_val * B_val), MSB first.
//
// 8 single-kernel shapes all plateau at 77-80% DRAM (~6.35 TB/s): the mixed
// 1:2 R/W turnaround ceiling. Test: split into a read-dominant pass (decode ->
// 16MB packed scratch) and a write-dominant pass (scratch -> 537MB output).
// Pure-direction DRAM streams should exceed the mixed-mode 78%; scratch is
// likely L2-resident for pass 2 (16MB << 126MB L2, L2 persists across
// launches). Extra traffic: +32MB (+4%). Fallback: fused R1 kernel.

#define THREADS 256
#define MAX_ROWS 4194304               // problem size; 16 MB scratch

__device__ uint32_t g_scratch[MAX_ROWS];

static __device__ __forceinline__ uint32_t bit_of(float f) {
    // inputs are exactly 0.0f (0x00000000) or 1.0f (0x3F800000): test bit 23
    return (__float_as_uint(f) >> 23) & 1u;
}

static __device__ __forceinline__ float decode_e4m3(float4 lo, float4 hi) {
    // lo = {S, E3, E2, E1}, hi = {E0, M2, M1, M0}
    uint32_t s = bit_of(lo.x);
    uint32_t e = (bit_of(lo.y) << 3) | (bit_of(lo.z) << 2) |
                 (bit_of(lo.w) << 1) |  bit_of(hi.x);
    uint32_t m = (bit_of(hi.y) << 2) | (bit_of(hi.z) << 1) | bit_of(hi.w);
    // normal: (8+m)*2^(e-10); subnormal: m*2^-9
    uint32_t M = e ? (8u + m) : m;
    int      E = e ? ((int)e - 10) : -9;
    float mag = (float)(int)M * __int_as_float((E + 127) << 23);
    // OR sign in so zero products keep their sign bit (-0.0 matters to the
    // reference's fp32 bitcast)
    return __uint_as_float(__float_as_uint(mag) | (s << 31));
}

static __device__ __forceinline__ float4 expand4(uint32_t t) {
    float4 o;
    o.x = __uint_as_float(((t >> 3) & 1u) * 0x3F800000u);
    o.y = __uint_as_float(((t >> 2) & 1u) * 0x3F800000u);
    o.z = __uint_as_float(((t >> 1) & 1u) * 0x3F800000u);
    o.w = __uint_as_float(( t        & 1u) * 0x3F800000u);
    return o;
}

// ---- pass 1: read-dominant. 268MB in -> 16MB packed product words --------
__global__ void __launch_bounds__(THREADS)
pass1_decode(const float4* __restrict__ A4,
             const float4* __restrict__ B4,
             int nrows) {
    const int row = blockIdx.x * THREADS + threadIdx.x;
    if (row >= nrows) return;
    const size_t r2 = 2 * (size_t)row;
    float4 a0 = __ldcs(&A4[r2]);
    float4 a1 = __ldcs(&A4[r2 + 1]);
    float4 b0 = __ldcs(&B4[r2]);
    float4 b1 = __ldcs(&B4[r2 + 1]);
    // scratch write left at default policy -> stays in L2 for pass 2
    g_scratch[row] = __float_as_uint(decode_e4m3(a0, a1) * decode_e4m3(b0, b1));
}

// ---- pass 2: write-dominant. 16MB (L2-hot) -> 537MB bit expansion --------
__global__ void __launch_bounds__(THREADS)
pass2_expand(float4* __restrict__ out4, int nrows) {
    const int tid  = threadIdx.x;
    const int lane = tid & 31;
    const int row  = blockIdx.x * THREADS + tid;

    uint32_t p = 0;
    if (row < nrows) p = g_scratch[row];   // coalesced 32b, mostly L2 hits

    // warp covers 32 rows -> 4KB contiguous output, 8 coalesced 512B stores
    // (proven R6 shuffle scheme): float4 q=k*32+lane, src row = k*4+(lane>>3),
    // bit group = lane&7.
    const int warp_row0 = row & ~31;
    float4* wout = out4 + (size_t)warp_row0 * 8;
    const int rows_left = nrows - warp_row0;
    if (rows_left <= 0) return;
    const int q_limit   = rows_left >= 32 ? 256 : rows_left * 8;
    const int g_shift   = 28 - ((lane & 7) << 2);
    const int src_base  = lane >> 3;

#pragma unroll
    for (int k = 0; k < 8; k++) {
        uint32_t ps = __shfl_sync(0xffffffffu, p, k * 4 + src_base);
        int q = k * 32 + lane;
        if (q < q_limit) __stcs(&wout[q], expand4(ps >> g_shift));
    }
}

// ---- fallback: fused R1 kernel (any nrows) -------------------------------
__global__ void __launch_bounds__(THREADS)
spike_fp8_mul_fused(const float4* __restrict__ A4,
                    const float4* __restrict__ B4,
                    float4* __restrict__ out4,
                    int nrows) {
    __shared__ uint32_t sh[THREADS];
    const int tid = threadIdx.x;
    const int row = blockIdx.x * THREADS + tid;

    uint32_t pbits = 0;
    if (row < nrows) {
        size_t r2 = 2 * (size_t)row;
        float4 a0 = __ldcs(&A4[r2]);
        float4 a1 = __ldcs(&A4[r2 + 1]);
        float4 b0 = __ldcs(&B4[r2]);
        float4 b1 = __ldcs(&B4[r2 + 1]);
        pbits = __float_as_uint(decode_e4m3(a0, a1) * decode_e4m3(b0, b1));
    }
    sh[tid] = pbits;
    __syncthreads();

    const int rows_left = nrows - blockIdx.x * THREADS;
    const int q_limit   = rows_left >= THREADS ? THREADS * 8 : rows_left * 8;
    float4* blk_out = out4 + (size_t)blockIdx.x * (THREADS * 8);
    const int g_shift = 28 - ((tid & 7) << 2);

#pragma unroll
    for (int k = 0; k < 8; k++) {
        int q = k * THREADS + tid;
        if (q < q_limit) __stcs(&blk_out[q], expand4(sh[q >> 3] >> g_shift));
    }
}

extern "C" void kernel_launch(void* const* d_in, const int* in_sizes, int n_in,
                              void* d_out, int out_size) {
    const float4* A4 = (const float4*)d_in[0];
    const float4* B4 = (const float4*)d_in[1];
    float4* out4 = (float4*)d_out;

    int nrows  = in_sizes[0] / 8;
    int blocks = (nrows + THREADS - 1) / THREADS;

    if (nrows <= MAX_ROWS) {
        pass1_decode<<<blocks, THREADS>>>(A4, B4, nrows);
        pass2_expand<<<blocks, THREADS>>>(out4, nrows);
    } else {
        spike_fp8_mul_fused<<<blocks, THREADS>>>(A4, B4, out4, nrows);
    }
}

// round 13
// speedup vs baseline: 1.0385x; 1.0385x over previous
#include <cuda_runtime.h>
#include <cstdint>

// SpikeFP8MulToFP32 — FINAL (session-best, reproduced 3x: 122.88/122.91/122.98us).
//   A, B: [N, 8] float 0/1 bit-vectors of fp8 e4m3 (order S,E3..E0,M2,M1,M0)
//   out : [N, 32] float 0/1 bit-vector of fp32(A_val * B_val), MSB (sign) first.
//
// Session conclusion (9 experiments): minimum traffic is 268MB reads + 537MB
// writes = 805MB. The chip's effective DRAM drain rate is ~6.4 TB/s — proven
// by a write-pure split kernel hitting the SAME 6.38 TB/s as every mixed
// kernel — so the floor is ~117us kernel time, which this kernel achieves
// (115.9-118.6us across 4 runs). All shape axes exhausted and neutral:
// staging (SMEM vs shuffle), ld/st width (128 vs 256-bit), persistence,
// barriers, per-thread MLP, predication, block size, R/W phase separation.
// Configuration:
//   - grid N/256 x 256 threads, 1 thread = 1 row
//   - 4x independent LDG.128 .cs (fully coalesced)
//   - fp8 decode in integer bits + 1 IEEE FMUL (bit-exact; preserves -0.0)
//   - SMEM stage of product words, then 8x coalesced STG.128 .cs per thread

static __device__ __forceinline__ uint32_t bit_of(float f) {
    // inputs are exactly 0.0f (0x00000000) or 1.0f (0x3F800000): test bit 23
    return (__float_as_uint(f) >> 23) & 1u;
}

static __device__ __forceinline__ float decode_e4m3(float4 lo, float4 hi) {
    // lo = {S, E3, E2, E1}, hi = {E0, M2, M1, M0}
    uint32_t s = bit_of(lo.x);
    uint32_t e = (bit_of(lo.y) << 3) | (bit_of(lo.z) << 2) |
                 (bit_of(lo.w) << 1) |  bit_of(hi.x);
    uint32_t m = (bit_of(hi.y) << 2) | (bit_of(hi.z) << 1) | bit_of(hi.w);
    // normal:    (8+m) * 2^(e-10)
    // subnormal:  m    * 2^(-9)
    uint32_t M = e ? (8u + m) : m;
    int      E = e ? ((int)e - 10) : -9;
    float mag = (float)(int)M * __int_as_float((E + 127) << 23);
    // OR the sign in so M==0 yields a correctly signed zero (-0.0 matters:
    // the reference's fp32 bitcast exposes the sign bit of zero products)
    return __uint_as_float(__float_as_uint(mag) | (s << 31));
}

__global__ void __launch_bounds__(256)
spike_fp8_mul_kernel(const float4* __restrict__ A4,
                     const float4* __restrict__ B4,
                     float4* __restrict__ out4,
                     int nrows) {
    __shared__ uint32_t sh[256];

    const int tid = threadIdx.x;
    const int row = blockIdx.x * 256 + tid;

    uint32_t pbits = 0;
    if (row < nrows) {
        // each row = 8 floats = 2 float4
        float4 a0 = __ldcs(&A4[2 * row + 0]);
        float4 a1 = __ldcs(&A4[2 * row + 1]);
        float4 b0 = __ldcs(&B4[2 * row + 0]);
        float4 b1 = __ldcs(&B4[2 * row + 1]);
        float va = decode_e4m3(a0, a1);
        float vb = decode_e4m3(b0, b1);
        pbits = __float_as_uint(va * vb);   // exact in fp32; IEEE sign-of-zero
    }
    sh[tid] = pbits;
    __syncthreads();

    // Block writes 256 rows * 32 floats = 2048 float4, fully coalesced.
    // float4 q covers output floats [4q .. 4q+3] of this block's tile:
    //   local row = q>>3, bit group g = q&7, out[j] = bit (31-j) of p.
    const int rows_left = nrows - blockIdx.x * 256;      // >0
    const int q_limit   = rows_left >= 256 ? 2048 : rows_left * 8;
    float4* blk_out = out4 + (size_t)blockIdx.x * 2048;

    const int g_shift = 28 - ((tid & 7) << 2);           // invariant over k

#pragma unroll
    for (int k = 0; k < 8; k++) {
        int q = (k << 8) + tid;
        if (q < q_limit) {
            uint32_t p = sh[q >> 3];                     // 8-lane broadcast
            uint32_t t = p >> g_shift;                   // bits [31-4g .. 28-4g] in t[3..0]
            float4 v;
            v.x = __uint_as_float(((t >> 3) & 1u) * 0x3F800000u);
            v.y = __uint_as_float(((t >> 2) & 1u) * 0x3F800000u);
            v.z = __uint_as_float(((t >> 1) & 1u) * 0x3F800000u);
            v.w = __uint_as_float(( t        & 1u) * 0x3F800000u);
            __stcs(&blk_out[q], v);
        }
    }
}

extern "C" void kernel_launch(void* const* d_in, const int* in_sizes, int n_in,
                              void* d_out, int out_size) {
    const float4* A4 = (const float4*)d_in[0];
    const float4* B4 = (const float4*)d_in[1];
    float4* out4 = (float4*)d_out;

    int nrows = in_sizes[0] / 8;
    int blocks = (nrows + 255) / 256;
    spike_fp8_mul_kernel<<<blocks, 256>>>(A4, B4, out4, nrows);
}